// round 14
// baseline (speedup 1.0000x reference)
#include <cuda_runtime.h>
#include <cuda_fp16.h>
#include <math.h>
#include <cstdint>

#define N_TOTAL 4096
#define HALF    2048
#define DIM     256
#define EPS     1e-6f
#define MARGIN  0.3f

#define BM    128
#define BN    256
#define ROWB  528                    // 512 B data + 16 B pad
#define A_BYTES (BM * ROWB)          // 67584
#define B_BYTES (BN * ROWB)          // 135168
#define NCTA  ((HALF / BM) * (HALF / BN))   // 128

// Scratch (allocation-free)
__device__ __half   g_h[N_TOTAL * DIM];
__device__ float    g_sq[N_TOTAL];
__device__ unsigned g_ap[N_TOTAL];   // d^2 max over positives (bits), init 0
__device__ unsigned g_an[N_TOTAL];   // d^2 min over negatives (bits), init +inf
__device__ unsigned g_done;          // completion ticket, reset by k_normalize

static __device__ __forceinline__ unsigned su32(const void* p) {
    return (unsigned)__cvta_generic_to_shared(p);
}

// ---------------------------------------------------------------------------
// Kernel 1: L2-normalize rows -> fp16 + fp32 squared norm; reinit buffers.
// TWO rows per warp with interleaved reductions (2x ILP on the latency path).
// ---------------------------------------------------------------------------
__global__ void k_normalize(const float* __restrict__ in) {
    int gw   = (blockIdx.x * blockDim.x + threadIdx.x) >> 5;   // 0..2047
    int lane = threadIdx.x & 31;
    int ra = gw * 2, rb = ra + 1;
    if (ra >= N_TOTAL) return;

    const float4* rowA = (const float4*)(in + (size_t)ra * DIM);
    const float4* rowB = (const float4*)(in + (size_t)rb * DIM);
    float4 a0 = rowA[lane], a1 = rowA[lane + 32];
    float4 b0 = rowB[lane], b1 = rowB[lane + 32];

    float sa = a0.x*a0.x + a0.y*a0.y + a0.z*a0.z + a0.w*a0.w
             + a1.x*a1.x + a1.y*a1.y + a1.z*a1.z + a1.w*a1.w;
    float sb = b0.x*b0.x + b0.y*b0.y + b0.z*b0.z + b0.w*b0.w
             + b1.x*b1.x + b1.y*b1.y + b1.z*b1.z + b1.w*b1.w;
    #pragma unroll
    for (int o = 16; o; o >>= 1) {
        sa += __shfl_xor_sync(0xffffffffu, sa, o);
        sb += __shfl_xor_sync(0xffffffffu, sb, o);
    }

    float inva = 1.0f / (sqrtf(sa) + EPS);
    float invb = 1.0f / (sqrtf(sb) + EPS);

    __half* HA = g_h + (size_t)ra * DIM;
    __half* HB = g_h + (size_t)rb * DIM;
    *(__half2*)(HA + 4*lane)         = __floats2half2_rn(a0.x*inva, a0.y*inva);
    *(__half2*)(HA + 4*lane + 2)     = __floats2half2_rn(a0.z*inva, a0.w*inva);
    *(__half2*)(HA + 128 + 4*lane)   = __floats2half2_rn(a1.x*inva, a1.y*inva);
    *(__half2*)(HA + 128 + 4*lane+2) = __floats2half2_rn(a1.z*inva, a1.w*inva);
    *(__half2*)(HB + 4*lane)         = __floats2half2_rn(b0.x*invb, b0.y*invb);
    *(__half2*)(HB + 4*lane + 2)     = __floats2half2_rn(b0.z*invb, b0.w*invb);
    *(__half2*)(HB + 128 + 4*lane)   = __floats2half2_rn(b1.x*invb, b1.y*invb);
    *(__half2*)(HB + 128 + 4*lane+2) = __floats2half2_rn(b1.z*invb, b1.w*invb);

    if (lane == 0) {
        g_sq[ra] = sa * inva * inva;   g_sq[rb] = sb * invb * invb;
        g_ap[ra] = 0u;                 g_ap[rb] = 0u;
        g_an[ra] = 0x7F800000u;        g_an[rb] = 0x7F800000u;
    }
    if (blockIdx.x == 0 && threadIdx.x == 0) g_done = 0u;
}

// ---------------------------------------------------------------------------
// Kernel 2: single-wave GEMM with fp16-ACCUMULATE mma.sync (probing the 2x
// f16-accum rate): each K=64 chunk accumulates in fp16, then promotes into
// fp32 accumulators. mt-halves processed separately to bound register
// pressure. 512 threads = 16 warps (2x8), warp tile 64x32. Progressive
// 4-chunk cp.async loads. Fused squared-distance mining + final loss.
// ---------------------------------------------------------------------------
__global__ void __launch_bounds__(512, 1) k_mine(const int* __restrict__ tgt,
                                                 float* __restrict__ out) {
    extern __shared__ __align__(128) char dyn[];   // A panel then B panel
    __shared__ unsigned s_rp[BM], s_rn[BM], s_cp[BN], s_cn[BN];
    __shared__ int   s_lr[BM], s_lc[BN];
    __shared__ float s_sqr[BM], s_sqc[BN];
    __shared__ float s_red[512];
    __shared__ unsigned s_ticket;

    const int tid  = threadIdx.x, lane = tid & 31, w = tid >> 5;
    const int row0 = blockIdx.y * BM;
    const int col0 = blockIdx.x * BN;

    if (tid < 128) {
        s_rp[tid] = 0u;  s_rn[tid] = 0x7F800000u;
        s_lr[tid]  = tgt[row0 + tid];
        s_sqr[tid] = g_sq[row0 + tid];
    }
    if (tid < 256) {
        s_cp[tid] = 0u;  s_cn[tid] = 0x7F800000u;
        s_lc[tid]  = tgt[HALF + col0 + tid];
        s_sqc[tid] = g_sq[HALF + col0 + tid];
    }

    const __half* Ag = g_h + (size_t)row0 * DIM;
    const __half* Bg = g_h + (size_t)(HALF + col0) * DIM;
    char* tA = dyn;
    char* tB = dyn + A_BYTES;

    // 4 progressive k-chunks; chunk c covers k [c*64, (c+1)*64).
    #pragma unroll
    for (int c = 0; c < 4; c++) {
        #pragma unroll
        for (int i = 0; i < 6; i++) {
            int id = tid + i * 512;                // 0..3071
            if (id < 1024) {
                int r = id >> 3, cc = id & 7;
                asm volatile("cp.async.cg.shared.global [%0], [%1], 16;"
                    :: "r"(su32(tA) + (unsigned)(r * ROWB + (c * 8 + cc) * 16)),
                       "l"(Ag + (size_t)r * DIM + c * 64 + cc * 8));
            } else {
                int b = id - 1024;
                int r = b >> 3, cc = b & 7;
                asm volatile("cp.async.cg.shared.global [%0], [%1], 16;"
                    :: "r"(su32(tB) + (unsigned)(r * ROWB + (c * 8 + cc) * 16)),
                       "l"(Bg + (size_t)r * DIM + c * 64 + cc * 8));
            }
        }
        asm volatile("cp.async.commit_group;" ::: "memory");
    }

    const int m0 = (w >> 3) * 64;              // {0, 64}
    const int n0 = (w & 7)  * 32;              // 0..224
    const unsigned aoff  = (unsigned)((lane & 15) * ROWB + (lane >> 4) * 16);
    const unsigned boff4 = (unsigned)(((lane & 7) + (lane >> 4) * 8) * ROWB
                                      + ((lane >> 3) & 1) * 16);
    const unsigned aT = su32(tA);
    const unsigned bT = su32(tB);

    float acc[4][4][4];
    #pragma unroll
    for (int mt = 0; mt < 4; mt++)
        #pragma unroll
        for (int nt = 0; nt < 4; nt++)
            #pragma unroll
            for (int q = 0; q < 4; q++) acc[mt][nt][q] = 0.0f;

    #pragma unroll
    for (int c = 0; c < 4; c++) {
        if (c == 0)      asm volatile("cp.async.wait_group 3;" ::: "memory");
        else if (c == 1) asm volatile("cp.async.wait_group 2;" ::: "memory");
        else if (c == 2) asm volatile("cp.async.wait_group 1;" ::: "memory");
        else             asm volatile("cp.async.wait_group 0;" ::: "memory");
        __syncthreads();

        #pragma unroll
        for (int h = 0; h < 2; h++) {          // mt-halves: {0,1} then {2,3}
            unsigned hacc[2][4][2];            // fp16x2 accumulators (chunk-local)
            #pragma unroll
            for (int m2 = 0; m2 < 2; m2++)
                #pragma unroll
                for (int nt = 0; nt < 4; nt++) {
                    hacc[m2][nt][0] = 0u; hacc[m2][nt][1] = 0u;
                }

            #pragma unroll
            for (int ks = 0; ks < 4; ks++) {   // K=16 steps within chunk
                const int kk = c * 4 + ks;
                unsigned a[2][4], b[2][4];
                #pragma unroll
                for (int m2 = 0; m2 < 2; m2++) {
                    unsigned ad = aT + (unsigned)((m0 + (h * 2 + m2) * 16) * ROWB
                                                   + kk * 32) + aoff;
                    asm volatile(
                        "ldmatrix.sync.aligned.m8n8.x4.shared.b16 {%0,%1,%2,%3}, [%4];"
                        : "=r"(a[m2][0]), "=r"(a[m2][1]), "=r"(a[m2][2]), "=r"(a[m2][3])
                        : "r"(ad));
                }
                #pragma unroll
                for (int np = 0; np < 2; np++) {
                    unsigned bd = bT + (unsigned)((n0 + np * 16) * ROWB + kk * 32) + boff4;
                    asm volatile(
                        "ldmatrix.sync.aligned.m8n8.x4.shared.b16 {%0,%1,%2,%3}, [%4];"
                        : "=r"(b[np][0]), "=r"(b[np][1]), "=r"(b[np][2]), "=r"(b[np][3])
                        : "r"(bd));
                }
                #pragma unroll
                for (int m2 = 0; m2 < 2; m2++)
                    #pragma unroll
                    for (int nt = 0; nt < 4; nt++) {
                        asm volatile(
                            "mma.sync.aligned.m16n8k16.row.col.f16.f16.f16.f16 "
                            "{%0,%1}, {%2,%3,%4,%5}, {%6,%7}, {%0,%1};"
                            : "+r"(hacc[m2][nt][0]), "+r"(hacc[m2][nt][1])
                            : "r"(a[m2][0]), "r"(a[m2][1]), "r"(a[m2][2]), "r"(a[m2][3]),
                              "r"(b[nt >> 1][(nt & 1) * 2]),
                              "r"(b[nt >> 1][(nt & 1) * 2 + 1]));
                    }
            }

            // Promote chunk's fp16 partials into fp32 accumulators.
            #pragma unroll
            for (int m2 = 0; m2 < 2; m2++)
                #pragma unroll
                for (int nt = 0; nt < 4; nt++) {
                    float2 f0 = __half22float2(*(__half2*)&hacc[m2][nt][0]);
                    float2 f1 = __half22float2(*(__half2*)&hacc[m2][nt][1]);
                    acc[h * 2 + m2][nt][0] += f0.x;
                    acc[h * 2 + m2][nt][1] += f0.y;
                    acc[h * 2 + m2][nt][2] += f1.x;
                    acc[h * 2 + m2][nt][3] += f1.y;
                }
        }
    }

    // Epilogue: SQUARED distance + masked hard mining (sqrt deferred).
    float lrp[8], lrn[8], lcp[8], lcn[8];
    #pragma unroll
    for (int i = 0; i < 8; i++) { lrp[i] = 0.0f; lrn[i] = INFINITY;
                                  lcp[i] = 0.0f; lcn[i] = INFINITY; }

    #pragma unroll
    for (int mt = 0; mt < 4; mt++) {
        #pragma unroll
        for (int h = 0; h < 2; h++) {
            int r = m0 + mt * 16 + h * 8 + (lane >> 2);
            float sr = s_sqr[r];
            int   lr = s_lr[r];
            #pragma unroll
            for (int nt = 0; nt < 4; nt++) {
                #pragma unroll
                for (int q = 0; q < 2; q++) {
                    int c = n0 + nt * 8 + ((lane & 3) << 1) + q;
                    float dot = acc[mt][nt][h * 2 + q];
                    float d2  = fmaxf(fmaf(-2.0f, dot, sr + s_sqc[c]), EPS);
                    int ri = mt * 2 + h, ci = nt * 2 + q;
                    if (lr == s_lc[c]) {
                        lrp[ri] = fmaxf(lrp[ri], d2);
                        lcp[ci] = fmaxf(lcp[ci], d2);
                    } else {
                        lrn[ri] = fminf(lrn[ri], d2);
                        lcn[ci] = fminf(lcn[ci], d2);
                    }
                }
            }
        }
    }

    #pragma unroll
    for (int i = 0; i < 8; i++) {
        int r = m0 + (i >> 1) * 16 + (i & 1) * 8 + (lane >> 2);
        if (lrp[i] > 0.0f)     atomicMax(&s_rp[r], __float_as_uint(lrp[i]));
        if (lrn[i] < INFINITY) atomicMin(&s_rn[r], __float_as_uint(lrn[i]));
    }
    #pragma unroll
    for (int j = 0; j < 8; j++) {
        int c = n0 + (j >> 1) * 8 + ((lane & 3) << 1) + (j & 1);
        if (lcp[j] > 0.0f)     atomicMax(&s_cp[c], __float_as_uint(lcp[j]));
        if (lcn[j] < INFINITY) atomicMin(&s_cn[c], __float_as_uint(lcn[j]));
    }
    __syncthreads();

    if (tid < 128) {
        atomicMax(&g_ap[row0 + tid], s_rp[tid]);
        atomicMin(&g_an[row0 + tid], s_rn[tid]);
    } else if (tid < 384) {
        int t = tid - 128;
        atomicMax(&g_ap[HALF + col0 + t], s_cp[t]);
        atomicMin(&g_an[HALF + col0 + t], s_cn[t]);
    }

    // ---- Fused final loss: last CTA to finish reduces all anchors. ----
    __threadfence();
    __syncthreads();
    if (tid == 0) s_ticket = atomicAdd(&g_done, 1u);
    __syncthreads();
    if (s_ticket != NCTA - 1) return;

    float sum = 0.0f;
    for (int i = tid; i < N_TOTAL; i += 512) {
        float ap = sqrtf(__uint_as_float(g_ap[i]));
        unsigned anb = g_an[i];
        float an = (anb == 0x7F800000u) ? 1.0f : sqrtf(__uint_as_float(anb));
        sum += fmaxf(ap - an + MARGIN, 0.0f);
    }
    s_red[tid] = sum;
    __syncthreads();
    #pragma unroll
    for (int s = 256; s; s >>= 1) {
        if (tid < s) s_red[tid] += s_red[tid + s];
        __syncthreads();
    }
    if (tid == 0) out[0] = s_red[0] / (float)N_TOTAL;
}

// ---------------------------------------------------------------------------
extern "C" void kernel_launch(void* const* d_in, const int* in_sizes, int n_in,
                              void* d_out, int out_size) {
    const float* inputs  = (const float*)d_in[0];
    const int*   targets = (const int*)d_in[1];
    (void)in_sizes; (void)n_in; (void)out_size;

    const int dyn_bytes = A_BYTES + B_BYTES;       // 202752 B
    static bool attr_set = false;
    if (!attr_set) {
        cudaFuncSetAttribute(k_mine, cudaFuncAttributeMaxDynamicSharedMemorySize,
                             dyn_bytes);
        attr_set = true;
    }

    k_normalize<<<N_TOTAL / 16, 256>>>(inputs);    // 256 blocks, 2 rows/warp
    dim3 grid(HALF / BN, HALF / BM);               // 8 x 16 = 128 CTAs, single wave
    k_mine<<<grid, 512, dyn_bytes>>>(targets, (float*)d_out);
}

// round 15
// speedup vs baseline: 1.0843x; 1.0843x over previous
#include <cuda_runtime.h>
#include <cuda_fp16.h>
#include <math.h>
#include <cstdint>

#define N_TOTAL 4096
#define HALF    2048
#define DIM     256
#define EPS     1e-6f
#define MARGIN  0.3f

#define BM    128
#define BN    256
#define ROWB  528                    // 512 B data + 16 B pad
#define A_BYTES (BM * ROWB)          // 67584
#define B_BYTES (BN * ROWB)          // 135168
#define NCTA  ((HALF / BM) * (HALF / BN))   // 128

// Scratch (allocation-free)
__device__ __half   g_h[N_TOTAL * DIM];
__device__ float    g_sq[N_TOTAL];
__device__ unsigned g_ap[N_TOTAL];   // d^2 max over positives (bits), init 0
__device__ unsigned g_an[N_TOTAL];   // d^2 min over negatives (bits), init +inf
__device__ unsigned g_done;          // completion ticket, reset by k_normalize

static __device__ __forceinline__ unsigned su32(const void* p) {
    return (unsigned)__cvta_generic_to_shared(p);
}

// ---------------------------------------------------------------------------
// Kernel 1: L2-normalize rows -> fp16 + fp32 squared norm; reinit buffers.
// TWO rows per warp with interleaved reductions (2x ILP on the latency path).
// ---------------------------------------------------------------------------
__global__ void k_normalize(const float* __restrict__ in) {
    int gw   = (blockIdx.x * blockDim.x + threadIdx.x) >> 5;   // 0..2047
    int lane = threadIdx.x & 31;
    int ra = gw * 2, rb = ra + 1;
    if (ra >= N_TOTAL) return;

    const float4* rowA = (const float4*)(in + (size_t)ra * DIM);
    const float4* rowB = (const float4*)(in + (size_t)rb * DIM);
    float4 a0 = rowA[lane], a1 = rowA[lane + 32];
    float4 b0 = rowB[lane], b1 = rowB[lane + 32];

    float sa = a0.x*a0.x + a0.y*a0.y + a0.z*a0.z + a0.w*a0.w
             + a1.x*a1.x + a1.y*a1.y + a1.z*a1.z + a1.w*a1.w;
    float sb = b0.x*b0.x + b0.y*b0.y + b0.z*b0.z + b0.w*b0.w
             + b1.x*b1.x + b1.y*b1.y + b1.z*b1.z + b1.w*b1.w;
    #pragma unroll
    for (int o = 16; o; o >>= 1) {
        sa += __shfl_xor_sync(0xffffffffu, sa, o);
        sb += __shfl_xor_sync(0xffffffffu, sb, o);
    }

    float inva = 1.0f / (sqrtf(sa) + EPS);
    float invb = 1.0f / (sqrtf(sb) + EPS);

    __half* HA = g_h + (size_t)ra * DIM;
    __half* HB = g_h + (size_t)rb * DIM;
    *(__half2*)(HA + 4*lane)         = __floats2half2_rn(a0.x*inva, a0.y*inva);
    *(__half2*)(HA + 4*lane + 2)     = __floats2half2_rn(a0.z*inva, a0.w*inva);
    *(__half2*)(HA + 128 + 4*lane)   = __floats2half2_rn(a1.x*inva, a1.y*inva);
    *(__half2*)(HA + 128 + 4*lane+2) = __floats2half2_rn(a1.z*inva, a1.w*inva);
    *(__half2*)(HB + 4*lane)         = __floats2half2_rn(b0.x*invb, b0.y*invb);
    *(__half2*)(HB + 4*lane + 2)     = __floats2half2_rn(b0.z*invb, b0.w*invb);
    *(__half2*)(HB + 128 + 4*lane)   = __floats2half2_rn(b1.x*invb, b1.y*invb);
    *(__half2*)(HB + 128 + 4*lane+2) = __floats2half2_rn(b1.z*invb, b1.w*invb);

    if (lane == 0) {
        g_sq[ra] = sa * inva * inva;   g_sq[rb] = sb * invb * invb;
        g_ap[ra] = 0u;                 g_ap[rb] = 0u;
        g_an[ra] = 0x7F800000u;        g_an[rb] = 0x7F800000u;
    }
    if (blockIdx.x == 0 && threadIdx.x == 0) g_done = 0u;
}

// ---------------------------------------------------------------------------
// Kernel 2: single-wave fp16 mma.sync GEMM (fp32 accumulate — measured at the
// legacy-HMMA issue roofline). 512 threads = 16 warps (2x8), warp tile 64x32,
// 128 regs/thread. Full-K panels in SMEM via 4 progressive cp.async commit
// groups. B fragments via x4 ldmatrix. Fused squared-distance hard mining +
// (last CTA) final loss.
// ---------------------------------------------------------------------------
__global__ void __launch_bounds__(512, 1) k_mine(const int* __restrict__ tgt,
                                                 float* __restrict__ out) {
    extern __shared__ __align__(128) char dyn[];   // A panel then B panel
    __shared__ unsigned s_rp[BM], s_rn[BM], s_cp[BN], s_cn[BN];
    __shared__ int   s_lr[BM], s_lc[BN];
    __shared__ float s_sqr[BM], s_sqc[BN];
    __shared__ float s_red[512];
    __shared__ unsigned s_ticket;

    const int tid  = threadIdx.x, lane = tid & 31, w = tid >> 5;
    const int row0 = blockIdx.y * BM;
    const int col0 = blockIdx.x * BN;

    if (tid < 128) {
        s_rp[tid] = 0u;  s_rn[tid] = 0x7F800000u;
        s_lr[tid]  = tgt[row0 + tid];
        s_sqr[tid] = g_sq[row0 + tid];
    }
    if (tid < 256) {
        s_cp[tid] = 0u;  s_cn[tid] = 0x7F800000u;
        s_lc[tid]  = tgt[HALF + col0 + tid];
        s_sqc[tid] = g_sq[HALF + col0 + tid];
    }

    const __half* Ag = g_h + (size_t)row0 * DIM;
    const __half* Bg = g_h + (size_t)(HALF + col0) * DIM;
    char* tA = dyn;
    char* tB = dyn + A_BYTES;

    // 4 progressive k-chunks; chunk c covers k [c*64, (c+1)*64).
    // Per chunk: A 128x8 + B 256x8 16B-chunks = 3072 -> 6 per thread.
    #pragma unroll
    for (int c = 0; c < 4; c++) {
        #pragma unroll
        for (int i = 0; i < 6; i++) {
            int id = tid + i * 512;                // 0..3071
            if (id < 1024) {
                int r = id >> 3, cc = id & 7;
                asm volatile("cp.async.cg.shared.global [%0], [%1], 16;"
                    :: "r"(su32(tA) + (unsigned)(r * ROWB + (c * 8 + cc) * 16)),
                       "l"(Ag + (size_t)r * DIM + c * 64 + cc * 8));
            } else {
                int b = id - 1024;
                int r = b >> 3, cc = b & 7;
                asm volatile("cp.async.cg.shared.global [%0], [%1], 16;"
                    :: "r"(su32(tB) + (unsigned)(r * ROWB + (c * 8 + cc) * 16)),
                       "l"(Bg + (size_t)r * DIM + c * 64 + cc * 8));
            }
        }
        asm volatile("cp.async.commit_group;" ::: "memory");
    }

    const int m0 = (w >> 3) * 64;              // {0, 64}
    const int n0 = (w & 7)  * 32;              // 0..224
    const unsigned aoff  = (unsigned)((lane & 15) * ROWB + (lane >> 4) * 16);
    const unsigned boff4 = (unsigned)(((lane & 7) + (lane >> 4) * 8) * ROWB
                                      + ((lane >> 3) & 1) * 16);
    const unsigned aT = su32(tA);
    const unsigned bT = su32(tB);

    float acc[4][4][4];
    #pragma unroll
    for (int mt = 0; mt < 4; mt++)
        #pragma unroll
        for (int nt = 0; nt < 4; nt++)
            #pragma unroll
            for (int q = 0; q < 4; q++) acc[mt][nt][q] = 0.0f;

    #pragma unroll
    for (int c = 0; c < 4; c++) {
        if (c == 0)      asm volatile("cp.async.wait_group 3;" ::: "memory");
        else if (c == 1) asm volatile("cp.async.wait_group 2;" ::: "memory");
        else if (c == 2) asm volatile("cp.async.wait_group 1;" ::: "memory");
        else             asm volatile("cp.async.wait_group 0;" ::: "memory");
        __syncthreads();

        #pragma unroll
        for (int ks = 0; ks < 4; ks++) {       // K=16 steps within chunk
            const int kk = c * 4 + ks;
            unsigned a[4][4], b[2][4];
            #pragma unroll
            for (int mt = 0; mt < 4; mt++) {
                unsigned ad = aT + (unsigned)((m0 + mt * 16) * ROWB + kk * 32) + aoff;
                asm volatile(
                    "ldmatrix.sync.aligned.m8n8.x4.shared.b16 {%0,%1,%2,%3}, [%4];"
                    : "=r"(a[mt][0]), "=r"(a[mt][1]), "=r"(a[mt][2]), "=r"(a[mt][3])
                    : "r"(ad));
            }
            #pragma unroll
            for (int np = 0; np < 2; np++) {   // x4 B load covers nt = 2np, 2np+1
                unsigned bd = bT + (unsigned)((n0 + np * 16) * ROWB + kk * 32) + boff4;
                asm volatile(
                    "ldmatrix.sync.aligned.m8n8.x4.shared.b16 {%0,%1,%2,%3}, [%4];"
                    : "=r"(b[np][0]), "=r"(b[np][1]), "=r"(b[np][2]), "=r"(b[np][3])
                    : "r"(bd));
            }
            #pragma unroll
            for (int mt = 0; mt < 4; mt++)
                #pragma unroll
                for (int nt = 0; nt < 4; nt++) {
                    asm volatile(
                        "mma.sync.aligned.m16n8k16.row.col.f32.f16.f16.f32 "
                        "{%0,%1,%2,%3}, {%4,%5,%6,%7}, {%8,%9}, {%0,%1,%2,%3};"
                        : "+f"(acc[mt][nt][0]), "+f"(acc[mt][nt][1]),
                          "+f"(acc[mt][nt][2]), "+f"(acc[mt][nt][3])
                        : "r"(a[mt][0]), "r"(a[mt][1]), "r"(a[mt][2]), "r"(a[mt][3]),
                          "r"(b[nt >> 1][(nt & 1) * 2]), "r"(b[nt >> 1][(nt & 1) * 2 + 1]));
                }
        }
    }

    // Epilogue: SQUARED distance + masked hard mining (sqrt deferred).
    float lrp[8], lrn[8], lcp[8], lcn[8];
    #pragma unroll
    for (int i = 0; i < 8; i++) { lrp[i] = 0.0f; lrn[i] = INFINITY;
                                  lcp[i] = 0.0f; lcn[i] = INFINITY; }

    #pragma unroll
    for (int mt = 0; mt < 4; mt++) {
        #pragma unroll
        for (int h = 0; h < 2; h++) {
            int r = m0 + mt * 16 + h * 8 + (lane >> 2);
            float sr = s_sqr[r];
            int   lr = s_lr[r];
            #pragma unroll
            for (int nt = 0; nt < 4; nt++) {
                #pragma unroll
                for (int q = 0; q < 2; q++) {
                    int c = n0 + nt * 8 + ((lane & 3) << 1) + q;
                    float dot = acc[mt][nt][h * 2 + q];
                    float d2  = fmaxf(fmaf(-2.0f, dot, sr + s_sqc[c]), EPS);
                    int ri = mt * 2 + h, ci = nt * 2 + q;
                    if (lr == s_lc[c]) {
                        lrp[ri] = fmaxf(lrp[ri], d2);
                        lcp[ci] = fmaxf(lcp[ci], d2);
                    } else {
                        lrn[ri] = fminf(lrn[ri], d2);
                        lcn[ci] = fminf(lcn[ci], d2);
                    }
                }
            }
        }
    }

    #pragma unroll
    for (int i = 0; i < 8; i++) {
        int r = m0 + (i >> 1) * 16 + (i & 1) * 8 + (lane >> 2);
        if (lrp[i] > 0.0f)     atomicMax(&s_rp[r], __float_as_uint(lrp[i]));
        if (lrn[i] < INFINITY) atomicMin(&s_rn[r], __float_as_uint(lrn[i]));
    }
    #pragma unroll
    for (int j = 0; j < 8; j++) {
        int c = n0 + (j >> 1) * 8 + ((lane & 3) << 1) + (j & 1);
        if (lcp[j] > 0.0f)     atomicMax(&s_cp[c], __float_as_uint(lcp[j]));
        if (lcn[j] < INFINITY) atomicMin(&s_cn[c], __float_as_uint(lcn[j]));
    }
    __syncthreads();

    if (tid < 128) {
        atomicMax(&g_ap[row0 + tid], s_rp[tid]);
        atomicMin(&g_an[row0 + tid], s_rn[tid]);
    } else if (tid < 384) {
        int t = tid - 128;
        atomicMax(&g_ap[HALF + col0 + t], s_cp[t]);
        atomicMin(&g_an[HALF + col0 + t], s_cn[t]);
    }

    // ---- Fused final loss: last CTA to finish reduces all anchors. ----
    __threadfence();
    __syncthreads();
    if (tid == 0) s_ticket = atomicAdd(&g_done, 1u);
    __syncthreads();
    if (s_ticket != NCTA - 1) return;

    float sum = 0.0f;
    for (int i = tid; i < N_TOTAL; i += 512) {
        float ap = sqrtf(__uint_as_float(g_ap[i]));
        unsigned anb = g_an[i];
        float an = (anb == 0x7F800000u) ? 1.0f : sqrtf(__uint_as_float(anb));
        sum += fmaxf(ap - an + MARGIN, 0.0f);
    }
    s_red[tid] = sum;
    __syncthreads();
    #pragma unroll
    for (int s = 256; s; s >>= 1) {
        if (tid < s) s_red[tid] += s_red[tid + s];
        __syncthreads();
    }
    if (tid == 0) out[0] = s_red[0] / (float)N_TOTAL;
}

// ---------------------------------------------------------------------------
extern "C" void kernel_launch(void* const* d_in, const int* in_sizes, int n_in,
                              void* d_out, int out_size) {
    const float* inputs  = (const float*)d_in[0];
    const int*   targets = (const int*)d_in[1];
    (void)in_sizes; (void)n_in; (void)out_size;

    const int dyn_bytes = A_BYTES + B_BYTES;       // 202752 B
    static bool attr_set = false;
    if (!attr_set) {
        cudaFuncSetAttribute(k_mine, cudaFuncAttributeMaxDynamicSharedMemorySize,
                             dyn_bytes);
        attr_set = true;
    }

    k_normalize<<<N_TOTAL / 16, 256>>>(inputs);    // 256 blocks, 2 rows/warp
    dim3 grid(HALF / BN, HALF / BM);               // 8 x 16 = 128 CTAs, single wave
    k_mine<<<grid, 512, dyn_bytes>>>(targets, (float*)d_out);
}